// round 14
// baseline (speedup 1.0000x reference)
#include <cuda_runtime.h>
#include <cstdint>

#define Bn 32
#define An 8400
#define NCn 80
#define Kn 1024
#define Gn 32
#define NSUPn 16
#define MAXDET 300

// -------- scratch (no allocs allowed) --------
__device__ unsigned long long g_keys[Bn * An];
__device__ unsigned long long g_sorted[Bn * Kn];
__device__ float4             g_sbox[Bn * Kn];    // unshifted boxes
__device__ float4             g_sboxs[Bn * Kn];   // class-shifted boxes
__device__ int                g_scls[Bn * Kn];
__device__ float              g_sconf[Bn * Kn];
__device__ int                g_keep[Bn * Kn];
__device__ int                g_nvalid[Bn];

// ============================================================
// Kernel 1: conf = max(scores) with 8-group tracking; keys only.
// ============================================================
__global__ void k1_scores(const float* __restrict__ preds) {
    const int APQ = An / 4;
    int t = blockIdx.x * blockDim.x + threadIdx.x;
    if (t >= Bn * APQ) return;
    int b  = t / APQ;
    int a4 = (t - b * APQ) * 4;
    const float* base = preds + (size_t)b * (4 + NCn) * An;

    float    fA[4][4];
    unsigned iA[4][4];
#pragma unroll
    for (int g = 0; g < 4; ++g)
#pragma unroll
        for (int k = 0; k < 4; ++k) { fA[g][k] = 0.f; iA[g][k] = 0u; }

#pragma unroll
    for (int j = 0; j < 40; ++j) {
        float4 s = *(const float4*)(base + (size_t)(4 + j) * An + a4);
        int g = j / 10;
        fA[g][0] = fmaxf(fA[g][0], s.x);
        fA[g][1] = fmaxf(fA[g][1], s.y);
        fA[g][2] = fmaxf(fA[g][2], s.z);
        fA[g][3] = fmaxf(fA[g][3], s.w);
    }
#pragma unroll
    for (int j = 40; j < 80; ++j) {
        float4 s = *(const float4*)(base + (size_t)(4 + j) * An + a4);
        int g = j / 10 - 4;
        iA[g][0] = max(iA[g][0], __float_as_uint(s.x));
        iA[g][1] = max(iA[g][1], __float_as_uint(s.y));
        iA[g][2] = max(iA[g][2], __float_as_uint(s.z));
        iA[g][3] = max(iA[g][3], __float_as_uint(s.w));
    }

#pragma unroll
    for (int k = 0; k < 4; ++k) {
        int a = a4 + k;
        float m01 = fmaxf(fA[0][k], fA[1][k]);
        float m23 = fmaxf(fA[2][k], fA[3][k]);
        float mF  = fmaxf(m01, m23);
        float m45 = fmaxf(__uint_as_float(iA[0][k]), __uint_as_float(iA[1][k]));
        float m67 = fmaxf(__uint_as_float(iA[2][k]), __uint_as_float(iA[3][k]));
        float m   = fmaxf(mF, fmaxf(m45, m67));
        unsigned mb = __float_as_uint(m);
        int g = (__float_as_uint(fA[0][k]) == mb) ? 0 :
                (__float_as_uint(fA[1][k]) == mb) ? 1 :
                (__float_as_uint(fA[2][k]) == mb) ? 2 :
                (__float_as_uint(fA[3][k]) == mb) ? 3 :
                (iA[0][k] == mb) ? 4 :
                (iA[1][k] == mb) ? 5 :
                (iA[2][k] == mb) ? 6 : 7;
        float tc = (m > 0.25f) ? m : 0.0f;
        unsigned low = ((0x3FFFu - (unsigned)a) << 3) | (unsigned)g;
        g_keys[(size_t)b * An + a] =
            ((unsigned long long)__float_as_uint(tc) << 32) | (unsigned long long)low;
    }
}

__device__ __forceinline__ float iou_rn(float ax1, float ay1, float ax2, float ay2, float areaA,
                                        float bx1, float by1, float bx2, float by2, float areaB) {
    float ltx = fmaxf(ax1, bx1), lty = fmaxf(ay1, by1);
    float rbx = fminf(ax2, bx2), rby = fminf(ay2, by2);
    float ww = fmaxf(__fsub_rn(rbx, ltx), 0.0f);
    float hh = fmaxf(__fsub_rn(rby, lty), 0.0f);
    float inter = __fmul_rn(ww, hh);
    float uni = __fadd_rn(__fsub_rn(__fadd_rn(areaA, areaB), inter), 1e-9f);
    return __fdiv_rn(inter, uni);
}

__device__ __forceinline__ int warp_incl_scan(int x, int lane) {
#pragma unroll
    for (int off = 1; off < 32; off <<= 1) {
        int y = __shfl_up_sync(0xFFFFFFFFu, x, off);
        if (lane >= off) x += y;
    }
    return x;
}

// ============================================================
// Kernel 2a: per-batch top-1024 (3-pass radix on conf word) + sort.
// Also emits g_nvalid[b] = #selected with conf > 0.
// ============================================================
__global__ __launch_bounds__(1024, 1) void k2a_select(void) {
    __shared__ unsigned s_hist4[4][2048];
    __shared__ unsigned long long s_key[Kn];
    __shared__ unsigned sh_pfx;
    __shared__ int sh_r, sh_cnt, sh_c, sh_tot;

    const int b = blockIdx.x;
    const int tid = threadIdx.x;
    const int lane = tid & 31;
    const int wid = tid >> 5;
    const unsigned lmask_lt = (1u << lane) - 1u;
    const unsigned long long* keys = g_keys + (size_t)b * An;

    if (tid == 0) { sh_pfx = 0u; sh_r = Kn - 1; sh_cnt = 0; sh_tot = 0; sh_c = 0; }

    unsigned hr[9];
#pragma unroll
    for (int it = 0; it < 9; ++it) {
        int idx = tid + it * 1024;
        hr[it] = (idx < An) ? (unsigned)(keys[idx] >> 32) : 0u;
    }
    const bool v8 = (tid < An - 8192);

    const int shifts[3] = {21, 10, 0};
    const int bitsA[3]  = {11, 11, 10};
    unsigned mask32 = 0u;
    for (int pass = 0; pass < 3; ++pass) {
        const int shift = shifts[pass];
        const unsigned dmask = (1u << bitsA[pass]) - 1u;
        const int NB = 1 << bitsA[pass];
#pragma unroll
        for (int z = 0; z < 8; ++z) ((unsigned*)s_hist4)[tid + z * 1024] = 0u;
        __syncthreads();
        unsigned pref = sh_pfx;
        const int hc = wid & 3;
#pragma unroll
        for (int it = 0; it < 9; ++it) {
            bool valid = (it < 8) || v8;
            int dig = (valid && ((hr[it] & mask32) == pref))
                        ? (int)((hr[it] >> shift) & dmask) : -1;
            unsigned m = __match_any_sync(0xFFFFFFFFu, dig);
            if (dig >= 0 && (m & lmask_lt) == 0u)
                atomicAdd(&s_hist4[hc][dig], (unsigned)__popc(m));
        }
        __syncthreads();
        for (int z = tid; z < NB; z += 1024)
            s_hist4[0][z] = s_hist4[0][z] + s_hist4[1][z] + s_hist4[2][z] + s_hist4[3][z];
        __syncthreads();
        if (tid < 32) {
            const int BPL = NB / 32;
            unsigned laneTot = 0;
            for (int j = 0; j < BPL; ++j)
                laneTot += s_hist4[0][lane * BPL + j];
            unsigned v = laneTot;
#pragma unroll
            for (int off = 1; off < 32; off <<= 1) {
                unsigned o = __shfl_down_sync(0xFFFFFFFFu, v, off);
                if (lane + off < 32) v += o;
            }
            unsigned exAbove = v - laneTot;
            unsigned r = (unsigned)sh_r;
            if (exAbove <= r && r < exAbove + laneTot) {
                unsigned running = exAbove;
                for (int j = BPL - 1; j >= 0; --j) {
                    int bin = lane * BPL + j;
                    unsigned c = s_hist4[0][bin];
                    if (running <= r && r < running + c) {
                        sh_pfx = pref | ((unsigned)bin << shift);
                        sh_r = (int)(r - running);
                        if (pass == 2) sh_c = (int)c;
                        break;
                    }
                    running += c;
                }
            }
        }
        mask32 |= (dmask << shift);
        __syncthreads();
    }
    const unsigned pfx = sh_pfx;
    const int r_fin = sh_r;
    const bool tie = (sh_c != r_fin + 1);

    if (!tie) {
#pragma unroll
        for (int it = 0; it < 9; ++it) {
            bool valid = (it < 8) || v8;
            bool sel = valid && (hr[it] >= pfx);
            unsigned bal = __ballot_sync(0xFFFFFFFFu, sel);
            if (bal) {
                int leader = __ffs(bal) - 1;
                int basep = 0;
                if (lane == leader) basep = atomicAdd(&sh_cnt, __popc(bal));
                basep = __shfl_sync(0xFFFFFFFFu, basep, leader);
                if (sel) {
                    int p = basep + __popc(bal & lmask_lt);
                    if (p < Kn) s_key[p] = keys[tid + it * 1024];
                }
            }
        }
    } else {
        unsigned lr[9];
#pragma unroll
        for (int it = 0; it < 9; ++it) {
            int idx = tid + it * 1024;
            lr[it] = (idx < An) ? (unsigned)keys[idx] : 0u;
        }
        unsigned T_low = 0u;
        for (int bit = 31; bit >= 0; --bit) {
            unsigned t2 = T_low | (1u << bit);
            int cnt = 0;
#pragma unroll
            for (int it = 0; it < 9; ++it) {
                bool valid = (it < 8) || v8;
                if (valid && hr[it] == pfx && lr[it] >= t2) cnt++;
            }
#pragma unroll
            for (int off = 16; off > 0; off >>= 1)
                cnt += __shfl_down_sync(0xFFFFFFFFu, cnt, off);
            if (lane == 0 && cnt) atomicAdd(&sh_tot, cnt);
            __syncthreads();
            int total = sh_tot;
            __syncthreads();
            if (tid == 0) sh_tot = 0;
            __syncthreads();
            if (total >= r_fin + 1) T_low = t2;
        }
#pragma unroll
        for (int it = 0; it < 9; ++it) {
            bool valid = (it < 8) || v8;
            bool sel = valid && ((hr[it] > pfx) || (hr[it] == pfx && lr[it] >= T_low));
            unsigned bal = __ballot_sync(0xFFFFFFFFu, sel);
            if (bal) {
                int leader = __ffs(bal) - 1;
                int basep = 0;
                if (lane == leader) basep = atomicAdd(&sh_cnt, __popc(bal));
                basep = __shfl_sync(0xFFFFFFFFu, basep, leader);
                if (sel) {
                    int p = basep + __popc(bal & lmask_lt);
                    if (p < Kn) s_key[p] = keys[tid + it * 1024];
                }
            }
        }
    }
    __syncthreads();

    unsigned long long v = s_key[tid];
    for (int kk = 2; kk <= Kn; kk <<= 1) {
        bool dirDesc = ((tid & kk) == 0);
        for (int j = kk >> 1; j > 0; j >>= 1) {
            unsigned long long pv;
            if (j >= 32) {
                __syncthreads();
                s_key[tid] = v;
                __syncthreads();
                pv = s_key[tid ^ j];
            } else {
                pv = __shfl_xor_sync(0xFFFFFFFFu, v, j);
            }
            bool iLower = (tid & j) == 0;
            bool takeMax = (iLower == dirDesc);
            if ((pv > v) == takeMax) v = pv;
        }
    }
    // conf>0 count (sorted descending => valid ranks are a prefix)
    int nv = __syncthreads_count((unsigned)(v >> 32) != 0u);
    if (tid == 0) g_nvalid[b] = nv;
    g_sorted[(size_t)b * Kn + tid] = v;
}

// ============================================================
// Kernel 2b: per selected anchor -- box decode + cls + packed
// shifted box. Full-chip scattered-load latency hiding.
// ============================================================
__global__ void k2b_gather(const float* __restrict__ preds) {
    int idx = blockIdx.x * 256 + threadIdx.x;   // [0, 32K)
    int b = idx >> 10;
    unsigned long long kk = g_sorted[idx];
    float cf = __uint_as_float((unsigned)(kk >> 32));
    unsigned low = (unsigned)kk;
    int a = 0x3FFF - (int)(low >> 3);
    int g = (int)(low & 7u);

    const float* base = preds + (size_t)b * (4 + NCn) * An;
    float cx = __ldg(base + (size_t)0 * An + a);
    float cy = __ldg(base + (size_t)1 * An + a);
    float w  = __ldg(base + (size_t)2 * An + a);
    float h  = __ldg(base + (size_t)3 * An + a);
    float hw = __fmul_rn(w, 0.5f);
    float hh = __fmul_rn(h, 0.5f);
    float x1 = __fsub_rn(cx, hw), y1 = __fsub_rn(cy, hh);
    float x2 = __fadd_rn(cx, hw), y2 = __fadd_rn(cy, hh);
    g_sbox[idx] = make_float4(x1, y1, x2, y2);
    g_sconf[idx] = cf;

    int c0 = g * 10;
    const float* sp = base + (size_t)(4 + c0) * An + a;
    float vv[10];
#pragma unroll
    for (int j = 0; j < 10; ++j) vv[j] = __ldg(sp + (size_t)j * An);
    int cls = c0;
#pragma unroll
    for (int j = 9; j >= 0; --j) if (vv[j] == cf) cls = c0 + j;
    g_scls[idx] = cls;

    float sa = __fmul_rn((float)cls, 7680.0f);
    g_sboxs[idx] = make_float4(__fadd_rn(x1, sa), __fadd_rn(y1, sa),
                               __fadd_rn(x2, sa), __fadd_rn(y2, sa));
}

// ============================================================
// Kernel 2c: ONE WARP PER (batch, class). 2560 single-warp blocks
// -> whole NMS is one wave; no smem, no __syncthreads, no intra-
// block load imbalance. List build via coalesced LDG + ballot/fns.
// ============================================================
__global__ __launch_bounds__(32) void k2c_nms(void) {
    const int blk = blockIdx.x;          // [0, Bn*NCn)
    const int b = blk / NCn;
    const int c = blk - b * NCn;
    const int lane = threadIdx.x;
    const size_t bi = (size_t)b * Kn;
    const int nvalid = g_nvalid[b];

    // register rank list via ballot + fns (ranks lane, lane+32)
    int i0 = -1, i1 = -1, pos = 0;
    for (int base = 0; base < Kn; base += 32) {
        bool mt = (g_scls[bi + base + lane] == c);
        unsigned m = __ballot_sync(0xFFFFFFFFu, mt);
        int cnt = __popc(m);
        if (lane >= pos && lane < pos + cnt)
            i0 = base + (int)__fns(m, 0, lane - pos + 1);
        int l2 = lane + 32;
        if (l2 >= pos && l2 < pos + cnt)
            i1 = base + (int)__fns(m, 0, l2 - pos + 1);
        pos += cnt;
    }
    const int n = pos;
    if (n == 0) return;

    if (n <= 64) {
        float4 B0 = make_float4(0.f, 0.f, 0.f, 0.f);
        float4 B1 = make_float4(0.f, 0.f, 0.f, 0.f);
        if (i0 >= 0) B0 = g_sboxs[bi + i0];
        if (i1 >= 0) B1 = g_sboxs[bi + i1];
        float ar0 = __fmul_rn(__fsub_rn(B0.z, B0.x), __fsub_rn(B0.w, B0.y));
        float ar1 = __fmul_rn(__fsub_rn(B1.z, B1.x), __fsub_rn(B1.w, B1.y));
        unsigned vlo = __ballot_sync(0xFFFFFFFFu, i0 >= 0 && i0 < nvalid);
        unsigned vhi = __ballot_sync(0xFFFFFFFFu, i1 >= 0 && i1 < nvalid);
        unsigned long long validm = (unsigned long long)vlo
                                  | ((unsigned long long)vhi << 32);

        unsigned long long keepm = 0ull;   // replicated in all lanes
        for (int m = 0; m < n; ++m) {
            int src = m & 31;
            float cx1 = __shfl_sync(0xFFFFFFFFu, (m < 32) ? B0.x : B1.x, src);
            float cy1 = __shfl_sync(0xFFFFFFFFu, (m < 32) ? B0.y : B1.y, src);
            float cx2 = __shfl_sync(0xFFFFFFFFu, (m < 32) ? B0.z : B1.z, src);
            float cy2 = __shfl_sync(0xFFFFFFFFu, (m < 32) ? B0.w : B1.w, src);
            float car = __shfl_sync(0xFFFFFFFFu, (m < 32) ? ar0  : ar1,  src);
            bool h0 = (lane < m) && ((keepm >> lane) & 1ull) &&
                      iou_rn(cx1, cy1, cx2, cy2, car,
                             B0.x, B0.y, B0.z, B0.w, ar0) > 0.45f;
            bool h1 = (lane + 32 < m) && ((keepm >> (lane + 32)) & 1ull) &&
                      iou_rn(cx1, cy1, cx2, cy2, car,
                             B1.x, B1.y, B1.z, B1.w, ar1) > 0.45f;
            bool sup = __any_sync(0xFFFFFFFFu, h0 | h1);
            bool kf = ((validm >> m) & 1ull) && !sup;
            keepm |= (unsigned long long)kf << m;
        }

        if (i0 >= 0) g_keep[bi + i0] = (int)((keepm >> lane) & 1ull);
        if (i1 >= 0) g_keep[bi + i1] = (int)((keepm >> (lane + 32)) & 1ull);
    } else {
        // exact fallback (rare): serial greedy, lane-parallel inner
        unsigned keepbits = 0u;   // bit q = keep of idx q*32+lane
        for (int m = 0; m < Kn; ++m) {
            if (g_scls[bi + m] != c) continue;
            float4 C = g_sboxs[bi + m];
            float car = __fmul_rn(__fsub_rn(C.z, C.x), __fsub_rn(C.w, C.y));
            bool kf;
            if (m >= nvalid) {
                kf = false;
            } else {
                bool hit = false;
                for (int base = 0; base < Kn; base += 32) {
                    int j = base + lane;
                    bool h2 = false;
                    if (j < m && g_scls[bi + j] == c &&
                        ((keepbits >> (base >> 5)) & 1u)) {
                        float4 J = g_sboxs[bi + j];
                        float jar = __fmul_rn(__fsub_rn(J.z, J.x), __fsub_rn(J.w, J.y));
                        h2 = iou_rn(C.x, C.y, C.z, C.w, car,
                                    J.x, J.y, J.z, J.w, jar) > 0.45f;
                    }
                    if (__any_sync(0xFFFFFFFFu, h2)) { hit = true; break; }
                }
                kf = !hit;
            }
            if ((m & 31) == lane && kf) keepbits |= 1u << (m >> 5);
        }
        for (int q = 0; q < 32; ++q) {
            int idx = q * 32 + lane;
            if (g_scls[bi + idx] == c)
                g_keep[bi + idx] = (int)((keepbits >> q) & 1u);
        }
    }
}

// ============================================================
// Kernel 2d: per-batch scan/cap + matching + stats.
// ============================================================
__global__ __launch_bounds__(1024, 1) void k2d_match(
    const float* __restrict__ gt_boxes,
    const int*   __restrict__ gt_cls,
    const int*   __restrict__ gt_mask,
    const int*   __restrict__ cat_to_super,
    float*       __restrict__ out)
{
    __shared__ float s_conf[Kn];
    __shared__ float s_x1[Kn], s_y1[Kn], s_x2[Kn], s_y2[Kn];
    __shared__ unsigned char s_cls[Kn], s_keep[Kn];
    __shared__ int s_scanw[32];
    __shared__ float s_gtb[Gn][4];
    __shared__ int   s_gtc[Gn], s_gtm[Gn], s_hit[Gn];
    __shared__ float s_biou[Gn], s_bconf[Gn];
    __shared__ float s_bins[96];

    const int b = blockIdx.x;
    const int tid = threadIdx.x;
    const int lane = tid & 31;
    const int wid = tid >> 5;
    const size_t bi = (size_t)b * Kn;

    if (tid < Gn) {
        s_gtc[tid] = gt_cls[b * Gn + tid];
        s_gtm[tid] = gt_mask[b * Gn + tid];
#pragma unroll
        for (int k = 0; k < 4; ++k)
            s_gtb[tid][k] = gt_boxes[(size_t)(b * Gn + tid) * 4 + k];
    }
    {
        s_conf[tid] = g_sconf[bi + tid];
        float4 bx = g_sbox[bi + tid];
        s_x1[tid] = bx.x; s_y1[tid] = bx.y; s_x2[tid] = bx.z; s_y2[tid] = bx.w;
        s_cls[tid] = (unsigned char)g_scls[bi + tid];
        s_keep[tid] = (unsigned char)g_keep[bi + tid];
    }
    __syncthreads();

    // scan keep; cap 300; pv
    int inc = warp_incl_scan((int)s_keep[tid], lane);
    if (lane == 31) s_scanw[wid] = inc;
    __syncthreads();
    if (tid < 32) s_scanw[tid] = warp_incl_scan(s_scanw[tid], tid);
    __syncthreads();
    int csum = inc + (wid > 0 ? s_scanw[wid - 1] : 0);
    int pv = (s_keep[tid] && csum <= MAXDET && s_conf[tid] > 0.5f) ? 1 : 0;
    int n_pred = __syncthreads_count(pv);
    s_keep[tid] = (unsigned char)pv;
    __syncthreads();

    // matching: one warp per GT
    {
        const int g = wid;
        float gx1 = s_gtb[g][0], gy1 = s_gtb[g][1], gx2 = s_gtb[g][2], gy2 = s_gtb[g][3];
        float areaG = __fmul_rn(__fsub_rn(gx2, gx1), __fsub_rn(gy2, gy1));
        int gc = s_gtc[g];
        float best = -__int_as_float(0x7f800000);
        int bidx = 0;
        for (int i = lane; i < Kn; i += 32) {
            float vv = -1.0f;
            if (s_keep[i] && (int)s_cls[i] == gc) {
                float ax1 = s_x1[i], ay1 = s_y1[i], ax2 = s_x2[i], ay2 = s_y2[i];
                float areaA = __fmul_rn(__fsub_rn(ax2, ax1), __fsub_rn(ay2, ay1));
                vv = iou_rn(ax1, ay1, ax2, ay2, areaA, gx1, gy1, gx2, gy2, areaG);
            }
            if (vv > best) { best = vv; bidx = i; }
        }
#pragma unroll
        for (int off = 16; off > 0; off >>= 1) {
            float ov = __shfl_down_sync(0xFFFFFFFFu, best, off);
            int   oi = __shfl_down_sync(0xFFFFFFFFu, bidx, off);
            if (ov > best || (ov == best && oi < bidx)) { best = ov; bidx = oi; }
        }
        if (lane == 0) {
            s_biou[g]  = best;
            s_bconf[g] = s_conf[bidx];
            s_hit[g]   = (best > 0.6f) && (s_gtm[g] != 0);
        }
    }
    __syncthreads();

    // final stats
    if (tid < 96) s_bins[tid] = 0.0f;
    __syncthreads();
    if (tid < 32) {
        int g = tid;
        float gm = (s_gtm[g] != 0) ? 1.0f : 0.0f;
        int gc = s_gtc[g];
        atomicAdd(&s_bins[gc], gm);
        atomicAdd(&s_bins[80 + cat_to_super[gc]], gm);
        float hi = s_hit[g] ? 1.0f : 0.0f;
        float n_gt = gm, n_hit = hi;
        float s_iou = hi * s_biou[g];
        float s_cf  = hi * s_bconf[g];
#pragma unroll
        for (int off = 16; off > 0; off >>= 1) {
            n_gt  += __shfl_down_sync(0xFFFFFFFFu, n_gt,  off);
            n_hit += __shfl_down_sync(0xFFFFFFFFu, n_hit, off);
            s_iou += __shfl_down_sync(0xFFFFFFFFu, s_iou, off);
            s_cf  += __shfl_down_sync(0xFFFFFFFFu, s_cf,  off);
        }
        if (tid == 0) {
            int mfc = 0;
            for (int c = 1; c < NCn; ++c) if (s_bins[c] > s_bins[mfc]) mfc = c;
            int mfs = 0;
            for (int s = 1; s < NSUPn; ++s) if (s_bins[80 + s] > s_bins[80 + mfs]) mfs = s;
            float fh = n_hit;
            float mean_iou  = __fdiv_rn(s_iou, fmaxf(fh, 1.0f));
            float mean_conf = (n_hit > 0.0f) ? __fdiv_rn(s_cf, fmaxf(fh, 1.0f)) : 1.0f;
            float correct   = __fdiv_rn(fh, fmaxf(n_gt, 1.0f));
            float r0, r1, r2, r3, r4;
            if (n_gt == 0.0f) {
                if (n_pred == 0) { r0 = 1.f; r1 = 1.f; r2 = -1.f; r3 = -1.f; r4 = 1.f; }
                else             { r0 = 0.f; r1 = 1.f; r2 = -2.f; r3 = -2.f; r4 = 0.f; }
            } else {
                r0 = mean_iou; r1 = mean_conf; r2 = (float)mfc; r3 = (float)mfs; r4 = correct;
            }
            out[b * 5 + 0] = r0; out[b * 5 + 1] = r1; out[b * 5 + 2] = r2;
            out[b * 5 + 3] = r3; out[b * 5 + 4] = r4;
        }
    }
}

extern "C" void kernel_launch(void* const* d_in, const int* in_sizes, int n_in,
                              void* d_out, int out_size) {
    const float* preds        = (const float*)d_in[0];
    const float* gt_boxes     = (const float*)d_in[1];
    const int*   gt_cls       = (const int*)d_in[2];
    const int*   gt_mask      = (const int*)d_in[3];
    const int*   cat_to_super = (const int*)d_in[4];
    float* out = (float*)d_out;

    int tot = Bn * (An / 4);
    k1_scores<<<(tot + 255) / 256, 256>>>(preds);
    k2a_select<<<Bn, 1024>>>();
    k2b_gather<<<(Bn * Kn) / 256, 256>>>(preds);
    k2c_nms<<<Bn * NCn, 32>>>();
    k2d_match<<<Bn, 1024>>>(gt_boxes, gt_cls, gt_mask, cat_to_super, out);
}

// round 15
// speedup vs baseline: 1.1236x; 1.1236x over previous
#include <cuda_runtime.h>
#include <cstdint>

#define Bn 32
#define An 8400
#define NCn 80
#define Kn 1024
#define Gn 32
#define NSUPn 16
#define MAXDET 300

// -------- scratch (no allocs allowed) --------
__device__ unsigned long long g_keys[Bn * An];
__device__ unsigned long long g_sorted[Bn * Kn];
__device__ float4             g_sbox[Bn * Kn];    // unshifted boxes
__device__ float4             g_sboxs[Bn * Kn];   // class-shifted boxes
__device__ int                g_scls[Bn * Kn];
__device__ float              g_sconf[Bn * Kn];
__device__ int                g_keep[Bn * Kn];
__device__ int                g_nvalid[Bn];

// ============================================================
// Kernel 1: conf = max(scores), 8-group tracking; keys only.
// ONE THREAD PER ANCHOR: scalar coalesced loads, ~8 accumulator
// regs -> near-full occupancy + deep load batching (MLP), no
// staging arrays (R9 spill lesson).
// ============================================================
__global__ __launch_bounds__(256) void k1_scores(const float* __restrict__ preds) {
    const int a = blockIdx.x * 256 + threadIdx.x;
    const int b = blockIdx.y;
    if (a >= An) return;
    const float* base = preds + (size_t)b * (4 + NCn) * An + a;

    float    fA[4];
    unsigned iA[4];
#pragma unroll
    for (int g = 0; g < 4; ++g) { fA[g] = 0.f; iA[g] = 0u; }

#pragma unroll
    for (int j = 0; j < 40; ++j) {
        float s = __ldg(base + (size_t)(4 + j) * An);
        fA[j / 10] = fmaxf(fA[j / 10], s);
    }
#pragma unroll
    for (int j = 40; j < 80; ++j) {
        float s = __ldg(base + (size_t)(4 + j) * An);
        iA[j / 10 - 4] = max(iA[j / 10 - 4], __float_as_uint(s));
    }

    float m01 = fmaxf(fA[0], fA[1]);
    float m23 = fmaxf(fA[2], fA[3]);
    float mF  = fmaxf(m01, m23);
    float m45 = fmaxf(__uint_as_float(iA[0]), __uint_as_float(iA[1]));
    float m67 = fmaxf(__uint_as_float(iA[2]), __uint_as_float(iA[3]));
    float m   = fmaxf(mF, fmaxf(m45, m67));
    unsigned mb = __float_as_uint(m);
    int g = (__float_as_uint(fA[0]) == mb) ? 0 :
            (__float_as_uint(fA[1]) == mb) ? 1 :
            (__float_as_uint(fA[2]) == mb) ? 2 :
            (__float_as_uint(fA[3]) == mb) ? 3 :
            (iA[0] == mb) ? 4 :
            (iA[1] == mb) ? 5 :
            (iA[2] == mb) ? 6 : 7;
    float tc = (m > 0.25f) ? m : 0.0f;
    unsigned low = ((0x3FFFu - (unsigned)a) << 3) | (unsigned)g;
    g_keys[(size_t)b * An + a] =
        ((unsigned long long)__float_as_uint(tc) << 32) | (unsigned long long)low;
}

__device__ __forceinline__ float iou_rn(float ax1, float ay1, float ax2, float ay2, float areaA,
                                        float bx1, float by1, float bx2, float by2, float areaB) {
    float ltx = fmaxf(ax1, bx1), lty = fmaxf(ay1, by1);
    float rbx = fminf(ax2, bx2), rby = fminf(ay2, by2);
    float ww = fmaxf(__fsub_rn(rbx, ltx), 0.0f);
    float hh = fmaxf(__fsub_rn(rby, lty), 0.0f);
    float inter = __fmul_rn(ww, hh);
    float uni = __fadd_rn(__fsub_rn(__fadd_rn(areaA, areaB), inter), 1e-9f);
    return __fdiv_rn(inter, uni);
}

__device__ __forceinline__ int warp_incl_scan(int x, int lane) {
#pragma unroll
    for (int off = 1; off < 32; off <<= 1) {
        int y = __shfl_up_sync(0xFFFFFFFFu, x, off);
        if (lane >= off) x += y;
    }
    return x;
}

// ============================================================
// Kernel 2a: per-batch top-1024 (3-pass radix on conf word) + sort.
// Also emits g_nvalid[b] = #selected with conf > 0.
// ============================================================
__global__ __launch_bounds__(1024, 1) void k2a_select(void) {
    __shared__ unsigned s_hist4[4][2048];
    __shared__ unsigned long long s_key[Kn];
    __shared__ unsigned sh_pfx;
    __shared__ int sh_r, sh_cnt, sh_c, sh_tot;

    const int b = blockIdx.x;
    const int tid = threadIdx.x;
    const int lane = tid & 31;
    const int wid = tid >> 5;
    const unsigned lmask_lt = (1u << lane) - 1u;
    const unsigned long long* keys = g_keys + (size_t)b * An;

    if (tid == 0) { sh_pfx = 0u; sh_r = Kn - 1; sh_cnt = 0; sh_tot = 0; sh_c = 0; }

    unsigned hr[9];
#pragma unroll
    for (int it = 0; it < 9; ++it) {
        int idx = tid + it * 1024;
        hr[it] = (idx < An) ? (unsigned)(keys[idx] >> 32) : 0u;
    }
    const bool v8 = (tid < An - 8192);

    const int shifts[3] = {21, 10, 0};
    const int bitsA[3]  = {11, 11, 10};
    unsigned mask32 = 0u;
    for (int pass = 0; pass < 3; ++pass) {
        const int shift = shifts[pass];
        const unsigned dmask = (1u << bitsA[pass]) - 1u;
        const int NB = 1 << bitsA[pass];
#pragma unroll
        for (int z = 0; z < 8; ++z) ((unsigned*)s_hist4)[tid + z * 1024] = 0u;
        __syncthreads();
        unsigned pref = sh_pfx;
        const int hc = wid & 3;
#pragma unroll
        for (int it = 0; it < 9; ++it) {
            bool valid = (it < 8) || v8;
            int dig = (valid && ((hr[it] & mask32) == pref))
                        ? (int)((hr[it] >> shift) & dmask) : -1;
            unsigned m = __match_any_sync(0xFFFFFFFFu, dig);
            if (dig >= 0 && (m & lmask_lt) == 0u)
                atomicAdd(&s_hist4[hc][dig], (unsigned)__popc(m));
        }
        __syncthreads();
        for (int z = tid; z < NB; z += 1024)
            s_hist4[0][z] = s_hist4[0][z] + s_hist4[1][z] + s_hist4[2][z] + s_hist4[3][z];
        __syncthreads();
        if (tid < 32) {
            const int BPL = NB / 32;
            unsigned laneTot = 0;
            for (int j = 0; j < BPL; ++j)
                laneTot += s_hist4[0][lane * BPL + j];
            unsigned v = laneTot;
#pragma unroll
            for (int off = 1; off < 32; off <<= 1) {
                unsigned o = __shfl_down_sync(0xFFFFFFFFu, v, off);
                if (lane + off < 32) v += o;
            }
            unsigned exAbove = v - laneTot;
            unsigned r = (unsigned)sh_r;
            if (exAbove <= r && r < exAbove + laneTot) {
                unsigned running = exAbove;
                for (int j = BPL - 1; j >= 0; --j) {
                    int bin = lane * BPL + j;
                    unsigned c = s_hist4[0][bin];
                    if (running <= r && r < running + c) {
                        sh_pfx = pref | ((unsigned)bin << shift);
                        sh_r = (int)(r - running);
                        if (pass == 2) sh_c = (int)c;
                        break;
                    }
                    running += c;
                }
            }
        }
        mask32 |= (dmask << shift);
        __syncthreads();
    }
    const unsigned pfx = sh_pfx;
    const int r_fin = sh_r;
    const bool tie = (sh_c != r_fin + 1);

    if (!tie) {
#pragma unroll
        for (int it = 0; it < 9; ++it) {
            bool valid = (it < 8) || v8;
            bool sel = valid && (hr[it] >= pfx);
            unsigned bal = __ballot_sync(0xFFFFFFFFu, sel);
            if (bal) {
                int leader = __ffs(bal) - 1;
                int basep = 0;
                if (lane == leader) basep = atomicAdd(&sh_cnt, __popc(bal));
                basep = __shfl_sync(0xFFFFFFFFu, basep, leader);
                if (sel) {
                    int p = basep + __popc(bal & lmask_lt);
                    if (p < Kn) s_key[p] = keys[tid + it * 1024];
                }
            }
        }
    } else {
        unsigned lr[9];
#pragma unroll
        for (int it = 0; it < 9; ++it) {
            int idx = tid + it * 1024;
            lr[it] = (idx < An) ? (unsigned)keys[idx] : 0u;
        }
        unsigned T_low = 0u;
        for (int bit = 31; bit >= 0; --bit) {
            unsigned t2 = T_low | (1u << bit);
            int cnt = 0;
#pragma unroll
            for (int it = 0; it < 9; ++it) {
                bool valid = (it < 8) || v8;
                if (valid && hr[it] == pfx && lr[it] >= t2) cnt++;
            }
#pragma unroll
            for (int off = 16; off > 0; off >>= 1)
                cnt += __shfl_down_sync(0xFFFFFFFFu, cnt, off);
            if (lane == 0 && cnt) atomicAdd(&sh_tot, cnt);
            __syncthreads();
            int total = sh_tot;
            __syncthreads();
            if (tid == 0) sh_tot = 0;
            __syncthreads();
            if (total >= r_fin + 1) T_low = t2;
        }
#pragma unroll
        for (int it = 0; it < 9; ++it) {
            bool valid = (it < 8) || v8;
            bool sel = valid && ((hr[it] > pfx) || (hr[it] == pfx && lr[it] >= T_low));
            unsigned bal = __ballot_sync(0xFFFFFFFFu, sel);
            if (bal) {
                int leader = __ffs(bal) - 1;
                int basep = 0;
                if (lane == leader) basep = atomicAdd(&sh_cnt, __popc(bal));
                basep = __shfl_sync(0xFFFFFFFFu, basep, leader);
                if (sel) {
                    int p = basep + __popc(bal & lmask_lt);
                    if (p < Kn) s_key[p] = keys[tid + it * 1024];
                }
            }
        }
    }
    __syncthreads();

    unsigned long long v = s_key[tid];
    for (int kk = 2; kk <= Kn; kk <<= 1) {
        bool dirDesc = ((tid & kk) == 0);
        for (int j = kk >> 1; j > 0; j >>= 1) {
            unsigned long long pv;
            if (j >= 32) {
                __syncthreads();
                s_key[tid] = v;
                __syncthreads();
                pv = s_key[tid ^ j];
            } else {
                pv = __shfl_xor_sync(0xFFFFFFFFu, v, j);
            }
            bool iLower = (tid & j) == 0;
            bool takeMax = (iLower == dirDesc);
            if ((pv > v) == takeMax) v = pv;
        }
    }
    // conf>0 count (sorted descending => valid ranks are a prefix)
    int nv = __syncthreads_count((unsigned)(v >> 32) != 0u);
    if (tid == 0) g_nvalid[b] = nv;
    g_sorted[(size_t)b * Kn + tid] = v;
}

// ============================================================
// Kernel 2b: per selected anchor -- box decode + cls + packed
// shifted box. Full-chip scattered-load latency hiding.
// ============================================================
__global__ void k2b_gather(const float* __restrict__ preds) {
    int idx = blockIdx.x * 256 + threadIdx.x;   // [0, 32K)
    int b = idx >> 10;
    unsigned long long kk = g_sorted[idx];
    float cf = __uint_as_float((unsigned)(kk >> 32));
    unsigned low = (unsigned)kk;
    int a = 0x3FFF - (int)(low >> 3);
    int g = (int)(low & 7u);

    const float* base = preds + (size_t)b * (4 + NCn) * An;
    float cx = __ldg(base + (size_t)0 * An + a);
    float cy = __ldg(base + (size_t)1 * An + a);
    float w  = __ldg(base + (size_t)2 * An + a);
    float h  = __ldg(base + (size_t)3 * An + a);
    float hw = __fmul_rn(w, 0.5f);
    float hh = __fmul_rn(h, 0.5f);
    float x1 = __fsub_rn(cx, hw), y1 = __fsub_rn(cy, hh);
    float x2 = __fadd_rn(cx, hw), y2 = __fadd_rn(cy, hh);
    g_sbox[idx] = make_float4(x1, y1, x2, y2);
    g_sconf[idx] = cf;

    int c0 = g * 10;
    const float* sp = base + (size_t)(4 + c0) * An + a;
    float vv[10];
#pragma unroll
    for (int j = 0; j < 10; ++j) vv[j] = __ldg(sp + (size_t)j * An);
    int cls = c0;
#pragma unroll
    for (int j = 9; j >= 0; --j) if (vv[j] == cf) cls = c0 + j;
    g_scls[idx] = cls;

    float sa = __fmul_rn((float)cls, 7680.0f);
    g_sboxs[idx] = make_float4(__fadd_rn(x1, sa), __fadd_rn(y1, sa),
                               __fadd_rn(x2, sa), __fadd_rn(y2, sa));
}

// ============================================================
// Kernel 2c: warp-per-(batch,class) NMS, 8 warps/block with smem
// class staging (R12 version -- best measured: 16.7us).
// ============================================================
__global__ __launch_bounds__(256, 4) void k2c_nms(void) {
    __shared__ unsigned char  s_clsb[Kn];
    __shared__ unsigned short s_l64[8][64];

    const int b  = blockIdx.x / 10;
    const int cg = blockIdx.x % 10;
    const int tid = threadIdx.x;
    const int lane = tid & 31;
    const int w = tid >> 5;
    const int c = cg * 8 + w;
    const unsigned lmask_lt = (1u << lane) - 1u;
    const size_t bi = (size_t)b * Kn;
    const int nvalid = g_nvalid[b];

    for (int i = tid; i < Kn; i += 256)
        s_clsb[i] = (unsigned char)g_scls[bi + i];
    __syncthreads();

    // ordered rank list for class c (first 64 ranks into smem)
    int pos = 0;
    for (int base = 0; base < Kn; base += 32) {
        bool mt = ((int)s_clsb[base + lane] == c);
        unsigned m = __ballot_sync(0xFFFFFFFFu, mt);
        if (mt) {
            int p = pos + __popc(m & lmask_lt);
            if (p < 64) s_l64[w][p] = (unsigned short)(base + lane);
        }
        pos += __popc(m);
    }
    const int n = pos;
    __syncwarp();
    if (n == 0) return;

    if (n <= 64) {
        int i0 = (lane < n)      ? (int)s_l64[w][lane]      : -1;
        int i1 = (lane + 32 < n) ? (int)s_l64[w][lane + 32] : -1;
        float4 B0 = make_float4(0.f, 0.f, 0.f, 0.f);
        float4 B1 = make_float4(0.f, 0.f, 0.f, 0.f);
        if (i0 >= 0) B0 = g_sboxs[bi + i0];
        if (i1 >= 0) B1 = g_sboxs[bi + i1];
        float ar0 = __fmul_rn(__fsub_rn(B0.z, B0.x), __fsub_rn(B0.w, B0.y));
        float ar1 = __fmul_rn(__fsub_rn(B1.z, B1.x), __fsub_rn(B1.w, B1.y));
        unsigned vlo = __ballot_sync(0xFFFFFFFFu, i0 >= 0 && i0 < nvalid);
        unsigned vhi = __ballot_sync(0xFFFFFFFFu, i1 >= 0 && i1 < nvalid);
        unsigned long long validm = (unsigned long long)vlo
                                  | ((unsigned long long)vhi << 32);

        unsigned long long keepm = 0ull;   // replicated in all lanes
        for (int m = 0; m < n; ++m) {
            int src = m & 31;
            float cx1 = __shfl_sync(0xFFFFFFFFu, (m < 32) ? B0.x : B1.x, src);
            float cy1 = __shfl_sync(0xFFFFFFFFu, (m < 32) ? B0.y : B1.y, src);
            float cx2 = __shfl_sync(0xFFFFFFFFu, (m < 32) ? B0.z : B1.z, src);
            float cy2 = __shfl_sync(0xFFFFFFFFu, (m < 32) ? B0.w : B1.w, src);
            float car = __shfl_sync(0xFFFFFFFFu, (m < 32) ? ar0  : ar1,  src);
            bool h0 = (lane < m) && ((keepm >> lane) & 1ull) &&
                      iou_rn(cx1, cy1, cx2, cy2, car,
                             B0.x, B0.y, B0.z, B0.w, ar0) > 0.45f;
            bool h1 = (lane + 32 < m) && ((keepm >> (lane + 32)) & 1ull) &&
                      iou_rn(cx1, cy1, cx2, cy2, car,
                             B1.x, B1.y, B1.z, B1.w, ar1) > 0.45f;
            bool sup = __any_sync(0xFFFFFFFFu, h0 | h1);
            bool kf = ((validm >> m) & 1ull) && !sup;
            keepm |= (unsigned long long)kf << m;
        }

        if (i0 >= 0) g_keep[bi + i0] = (int)((keepm >> lane) & 1ull);
        if (i1 >= 0) g_keep[bi + i1] = (int)((keepm >> (lane + 32)) & 1ull);
    } else {
        // exact fallback (rare): serial greedy, lane-parallel inner
        unsigned keepbits = 0u;   // bit q = keep of idx q*32+lane
        for (int m = 0; m < Kn; ++m) {
            if ((int)s_clsb[m] != c) continue;
            float4 C = g_sboxs[bi + m];
            float car = __fmul_rn(__fsub_rn(C.z, C.x), __fsub_rn(C.w, C.y));
            bool kf;
            if (m >= nvalid) {
                kf = false;
            } else {
                bool hit = false;
                for (int base = 0; base < Kn; base += 32) {
                    int j = base + lane;
                    bool h2 = false;
                    if (j < m && (int)s_clsb[j] == c &&
                        ((keepbits >> (base >> 5)) & 1u)) {
                        float4 J = g_sboxs[bi + j];
                        float jar = __fmul_rn(__fsub_rn(J.z, J.x), __fsub_rn(J.w, J.y));
                        h2 = iou_rn(C.x, C.y, C.z, C.w, car,
                                    J.x, J.y, J.z, J.w, jar) > 0.45f;
                    }
                    if (__any_sync(0xFFFFFFFFu, h2)) { hit = true; break; }
                }
                kf = !hit;
            }
            if ((m & 31) == lane && kf) keepbits |= 1u << (m >> 5);
        }
        for (int q = 0; q < 32; ++q) {
            int idx = q * 32 + lane;
            if ((int)s_clsb[idx] == c)
                g_keep[bi + idx] = (int)((keepbits >> q) & 1u);
        }
    }
}

// ============================================================
// Kernel 2d: per-batch scan/cap + matching + stats.
// ============================================================
__global__ __launch_bounds__(1024, 1) void k2d_match(
    const float* __restrict__ gt_boxes,
    const int*   __restrict__ gt_cls,
    const int*   __restrict__ gt_mask,
    const int*   __restrict__ cat_to_super,
    float*       __restrict__ out)
{
    __shared__ float s_conf[Kn];
    __shared__ float s_x1[Kn], s_y1[Kn], s_x2[Kn], s_y2[Kn];
    __shared__ unsigned char s_cls[Kn], s_keep[Kn];
    __shared__ int s_scanw[32];
    __shared__ float s_gtb[Gn][4];
    __shared__ int   s_gtc[Gn], s_gtm[Gn], s_hit[Gn];
    __shared__ float s_biou[Gn], s_bconf[Gn];
    __shared__ float s_bins[96];

    const int b = blockIdx.x;
    const int tid = threadIdx.x;
    const int lane = tid & 31;
    const int wid = tid >> 5;
    const size_t bi = (size_t)b * Kn;

    if (tid < Gn) {
        s_gtc[tid] = gt_cls[b * Gn + tid];
        s_gtm[tid] = gt_mask[b * Gn + tid];
#pragma unroll
        for (int k = 0; k < 4; ++k)
            s_gtb[tid][k] = gt_boxes[(size_t)(b * Gn + tid) * 4 + k];
    }
    {
        s_conf[tid] = g_sconf[bi + tid];
        float4 bx = g_sbox[bi + tid];
        s_x1[tid] = bx.x; s_y1[tid] = bx.y; s_x2[tid] = bx.z; s_y2[tid] = bx.w;
        s_cls[tid] = (unsigned char)g_scls[bi + tid];
        s_keep[tid] = (unsigned char)g_keep[bi + tid];
    }
    __syncthreads();

    // scan keep; cap 300; pv
    int inc = warp_incl_scan((int)s_keep[tid], lane);
    if (lane == 31) s_scanw[wid] = inc;
    __syncthreads();
    if (tid < 32) s_scanw[tid] = warp_incl_scan(s_scanw[tid], tid);
    __syncthreads();
    int csum = inc + (wid > 0 ? s_scanw[wid - 1] : 0);
    int pv = (s_keep[tid] && csum <= MAXDET && s_conf[tid] > 0.5f) ? 1 : 0;
    int n_pred = __syncthreads_count(pv);
    s_keep[tid] = (unsigned char)pv;
    __syncthreads();

    // matching: one warp per GT
    {
        const int g = wid;
        float gx1 = s_gtb[g][0], gy1 = s_gtb[g][1], gx2 = s_gtb[g][2], gy2 = s_gtb[g][3];
        float areaG = __fmul_rn(__fsub_rn(gx2, gx1), __fsub_rn(gy2, gy1));
        int gc = s_gtc[g];
        float best = -__int_as_float(0x7f800000);
        int bidx = 0;
        for (int i = lane; i < Kn; i += 32) {
            float vv = -1.0f;
            if (s_keep[i] && (int)s_cls[i] == gc) {
                float ax1 = s_x1[i], ay1 = s_y1[i], ax2 = s_x2[i], ay2 = s_y2[i];
                float areaA = __fmul_rn(__fsub_rn(ax2, ax1), __fsub_rn(ay2, ay1));
                vv = iou_rn(ax1, ay1, ax2, ay2, areaA, gx1, gy1, gx2, gy2, areaG);
            }
            if (vv > best) { best = vv; bidx = i; }
        }
#pragma unroll
        for (int off = 16; off > 0; off >>= 1) {
            float ov = __shfl_down_sync(0xFFFFFFFFu, best, off);
            int   oi = __shfl_down_sync(0xFFFFFFFFu, bidx, off);
            if (ov > best || (ov == best && oi < bidx)) { best = ov; bidx = oi; }
        }
        if (lane == 0) {
            s_biou[g]  = best;
            s_bconf[g] = s_conf[bidx];
            s_hit[g]   = (best > 0.6f) && (s_gtm[g] != 0);
        }
    }
    __syncthreads();

    // final stats
    if (tid < 96) s_bins[tid] = 0.0f;
    __syncthreads();
    if (tid < 32) {
        int g = tid;
        float gm = (s_gtm[g] != 0) ? 1.0f : 0.0f;
        int gc = s_gtc[g];
        atomicAdd(&s_bins[gc], gm);
        atomicAdd(&s_bins[80 + cat_to_super[gc]], gm);
        float hi = s_hit[g] ? 1.0f : 0.0f;
        float n_gt = gm, n_hit = hi;
        float s_iou = hi * s_biou[g];
        float s_cf  = hi * s_bconf[g];
#pragma unroll
        for (int off = 16; off > 0; off >>= 1) {
            n_gt  += __shfl_down_sync(0xFFFFFFFFu, n_gt,  off);
            n_hit += __shfl_down_sync(0xFFFFFFFFu, n_hit, off);
            s_iou += __shfl_down_sync(0xFFFFFFFFu, s_iou, off);
            s_cf  += __shfl_down_sync(0xFFFFFFFFu, s_cf,  off);
        }
        if (tid == 0) {
            int mfc = 0;
            for (int c = 1; c < NCn; ++c) if (s_bins[c] > s_bins[mfc]) mfc = c;
            int mfs = 0;
            for (int s = 1; s < NSUPn; ++s) if (s_bins[80 + s] > s_bins[80 + mfs]) mfs = s;
            float fh = n_hit;
            float mean_iou  = __fdiv_rn(s_iou, fmaxf(fh, 1.0f));
            float mean_conf = (n_hit > 0.0f) ? __fdiv_rn(s_cf, fmaxf(fh, 1.0f)) : 1.0f;
            float correct   = __fdiv_rn(fh, fmaxf(n_gt, 1.0f));
            float r0, r1, r2, r3, r4;
            if (n_gt == 0.0f) {
                if (n_pred == 0) { r0 = 1.f; r1 = 1.f; r2 = -1.f; r3 = -1.f; r4 = 1.f; }
                else             { r0 = 0.f; r1 = 1.f; r2 = -2.f; r3 = -2.f; r4 = 0.f; }
            } else {
                r0 = mean_iou; r1 = mean_conf; r2 = (float)mfc; r3 = (float)mfs; r4 = correct;
            }
            out[b * 5 + 0] = r0; out[b * 5 + 1] = r1; out[b * 5 + 2] = r2;
            out[b * 5 + 3] = r3; out[b * 5 + 4] = r4;
        }
    }
}

extern "C" void kernel_launch(void* const* d_in, const int* in_sizes, int n_in,
                              void* d_out, int out_size) {
    const float* preds        = (const float*)d_in[0];
    const float* gt_boxes     = (const float*)d_in[1];
    const int*   gt_cls       = (const int*)d_in[2];
    const int*   gt_mask      = (const int*)d_in[3];
    const int*   cat_to_super = (const int*)d_in[4];
    float* out = (float*)d_out;

    dim3 g1((An + 255) / 256, Bn);
    k1_scores<<<g1, 256>>>(preds);
    k2a_select<<<Bn, 1024>>>();
    k2b_gather<<<(Bn * Kn) / 256, 256>>>(preds);
    k2c_nms<<<Bn * 10, 256>>>();
    k2d_match<<<Bn, 1024>>>(gt_boxes, gt_cls, gt_mask, cat_to_super, out);
}